// round 10
// baseline (speedup 1.0000x reference)
#include <cuda_runtime.h>

// Problem constants (fixed shapes)
#define T_TOK 8192
#define D_IN  1024
#define H1    128
#define QDIM  32
#define HALFD 8
#define KNN   8
#define NKEYS 256

// GEMM tiling: 32 tokens x 128 outputs per block, BK=16, 128 threads.
#define BM 32
#define BN 128
#define BK 16
#define NKT (D_IN / BK)   // 64

// Scratch (device globals: allocation-free rule)
__device__ __align__(16) float g_h[T_TOK * H1];     // 4 MB (relu'd hidden)
__device__ float g_wt[T_TOK * 16];                  // 512 KB
__device__ int   g_id[T_TOK * 16];                  // 512 KB

// Packed dual-fp32 FMA (B300 FFMA2 path)
#define FMA2(d, a, b) asm("fma.rn.f32x2 %0, %1, %2, %0;" : "+l"(d) : "l"(a), "l"(b))

// ---------------------------------------------------------------------------
// Kernel 1: h = relu(x @ W1^T + b1)
//   grid 256 (2 CTAs/SM -> 2 warps/SMSP), 128 threads.
//   Xs [k][tok] (STS bank = lane, conflict-free), Ws [k][colpair] float4 with
//   duplicated (w,w) pairs so one LDS.128 feeds two FMA2 columns.
//   Per k-step: 1 LDS.128 (X) + 4 LDS.128 (W) + 16 FMA2.
// ---------------------------------------------------------------------------
__global__ __launch_bounds__(128, 1)
void k1_gemm_relu(const float* __restrict__ x, const float* __restrict__ W1,
                  const float* __restrict__ b1)
{
    __shared__ __align__(16) float  Xs[2][BK * BM];          // 2 x 2 KB
    __shared__ __align__(16) float4 Ws[2][BK * (BN / 2)];    // 2 x 16 KB

    const int tid  = threadIdx.x;
    const int lane = tid & 31;
    const int w    = tid >> 5;     // warp 0..3
    const int tx   = tid & 15;     // col-pair group
    const int ty   = tid >> 4;     // token quad 0..7
    const int t0   = blockIdx.x * BM;

    // Loader mapping
    const int xk  = w << 2;                   // X k-offset (one float4 per thread)
    const int wc0 = lane + ((w & 1) << 5);    // W col base; second col = +64
    const int wk0 = (w >> 1) << 2;            // W k-offset base; second quad = +8
    const int kqA = (w >> 1);                 // k-quad indices
    const int kqB = (w >> 1) + 2;

    const float* xp  = x  + (size_t)(t0 + lane) * D_IN + xk;
    const float* wp0 = W1 + (size_t)wc0 * D_IN + wk0;
    const float* wp1 = W1 + (size_t)(wc0 + 64) * D_IN + wk0;

    unsigned long long acc[2][8];
#pragma unroll
    for (int i = 0; i < 2; i++)
#pragma unroll
        for (int j = 0; j < 8; j++) acc[i][j] = 0ull;

    float4 px, pw00, pw01, pw10, pw11;

    // Prefetch tile 0
    px   = *(const float4*)(xp);
    pw00 = *(const float4*)(wp0);
    pw01 = *(const float4*)(wp0 + 8);
    pw10 = *(const float4*)(wp1);
    pw11 = *(const float4*)(wp1 + 8);

    // STS helpers: Xs bank = lane (conflict-free); Ws contiguous 8B per lane.
#define STW(buf, kq, col, v)                                                    \
    do {                                                                        \
        float2* wsp = (float2*)&Ws[buf][0];                                     \
        const int base = (((kq) << 2) * 64 + ((col) >> 1)) * 2 + ((col) & 1);   \
        wsp[base + 0 * 128] = make_float2((v).x, (v).x);                        \
        wsp[base + 1 * 128] = make_float2((v).y, (v).y);                        \
        wsp[base + 2 * 128] = make_float2((v).z, (v).z);                        \
        wsp[base + 3 * 128] = make_float2((v).w, (v).w);                        \
    } while (0)

#define STORE_TILE(buf)                                                         \
    do {                                                                        \
        Xs[buf][(xk + 0) * BM + lane] = px.x;                                   \
        Xs[buf][(xk + 1) * BM + lane] = px.y;                                   \
        Xs[buf][(xk + 2) * BM + lane] = px.z;                                   \
        Xs[buf][(xk + 3) * BM + lane] = px.w;                                   \
        STW(buf, kqA, wc0,      pw00);                                          \
        STW(buf, kqB, wc0,      pw01);                                          \
        STW(buf, kqA, wc0 + 64, pw10);                                          \
        STW(buf, kqB, wc0 + 64, pw11);                                          \
    } while (0)

    STORE_TILE(0);
    __syncthreads();

#pragma unroll 1
    for (int kt = 0; kt < NKT; kt++) {
        const int cur = kt & 1;
        if (kt < NKT - 1) {
            const int k0 = (kt + 1) * BK;
            px   = *(const float4*)(xp + k0);
            pw00 = *(const float4*)(wp0 + k0);
            pw01 = *(const float4*)(wp0 + k0 + 8);
            pw10 = *(const float4*)(wp1 + k0);
            pw11 = *(const float4*)(wp1 + k0 + 8);
        }
#pragma unroll
        for (int k = 0; k < BK; k++) {
            const ulonglong2 aa =
                *(const ulonglong2*)&Xs[cur][k * BM + (ty << 2)];
#pragma unroll
            for (int c = 0; c < 4; c++) {
                const ulonglong2 bb =
                    *(const ulonglong2*)&Ws[cur][k * 64 + tx + (c << 4)];
                FMA2(acc[0][2 * c],     aa.x, bb.x);
                FMA2(acc[0][2 * c + 1], aa.x, bb.y);
                FMA2(acc[1][2 * c],     aa.y, bb.x);
                FMA2(acc[1][2 * c + 1], aa.y, bb.y);
            }
        }
        if (kt < NKT - 1) STORE_TILE(cur ^ 1);
        __syncthreads();
    }

    // Epilogue: bias + relu
#pragma unroll
    for (int c = 0; c < 4; c++) {
#pragma unroll
        for (int par = 0; par < 2; par++) {
            const int j = (tx << 1) + (c << 5) + par;
            const float bias = __ldg(b1 + j);
#pragma unroll
            for (int i = 0; i < 2; i++) {
                const unsigned long long v = acc[i][2 * c + par];
                const int r = t0 + (ty << 2) + (i << 1);
                const float lo = __uint_as_float((unsigned)(v & 0xffffffffull)) + bias;
                const float hi = __uint_as_float((unsigned)(v >> 32)) + bias;
                g_h[(size_t)r * H1 + j]       = fmaxf(lo, 0.0f);
                g_h[(size_t)(r + 1) * H1 + j] = fmaxf(hi, 0.0f);
            }
        }
    }
}

// ---------------------------------------------------------------------------
// Kernel 3 (fused q-projection + top-k + combine + softmax).
// Warp per token. q_c computed per-lane from L1-resident W2 rows.
// Tie-breaking matches lax.top_k (lowest index first).
// ---------------------------------------------------------------------------
__global__ __launch_bounds__(256, 1)
void k3_topk(const float* __restrict__ keys, const float* __restrict__ W2,
             const float* __restrict__ b2)
{
    __shared__ __align__(16) float ks[2 * 2 * NKEYS * HALFD];   // 32 KB
    __shared__ __align__(16) float hs[8][H1];                   // 4 KB
    __shared__ float sc_s[8][2][2][KNN];
    __shared__ int   id_s[8][2][2][KNN];
    __shared__ float fsc_s[8][2][KNN];
    __shared__ int   fid_s[8][2][KNN];

    const int tid = threadIdx.x;
    for (int i = tid; i < 2 * 2 * NKEYS * HALFD; i += 256) ks[i] = keys[i];
    __syncthreads();

    const int w    = tid >> 5;
    const int lane = tid & 31;
    const int t    = blockIdx.x * 8 + w;
    const float NEGINF = __uint_as_float(0xff800000u);

    // ---- fused k2: q[lane] = b2[lane] + h[t] . W2[lane,:] ----
    ((float4*)&hs[w][0])[lane] =
        *(const float4*)(g_h + (size_t)t * H1 + (lane << 2));
    __syncwarp();

    float myq = __ldg(b2 + lane);
    {
        const float4* w2r = (const float4*)(W2 + (size_t)lane * H1);
#pragma unroll
        for (int j4 = 0; j4 < H1 / 4; j4++) {
            const float4 wv = __ldg(w2r + j4);
            const float4 h4 = *(const float4*)&hs[w][j4 << 2];
            myq = fmaf(h4.x, wv.x, myq);
            myq = fmaf(h4.y, wv.y, myq);
            myq = fmaf(h4.z, wv.z, myq);
            myq = fmaf(h4.w, wv.w, myq);
        }
    }
    __syncwarp();

    // ---- 4 units: (head, side) top-8 of 256 ----
#pragma unroll
    for (int u = 0; u < 4; u++) {
        const int h = u >> 1, side = u & 1;
        float qv[HALFD];
#pragma unroll
        for (int c = 0; c < HALFD; c++)
            qv[c] = __shfl_sync(0xffffffffu, myq, h * 16 + side * 8 + c);

        float s[8];  // lane owns keys n = i*32 + lane
#pragma unroll
        for (int i = 0; i < 8; i++) {
            const int n = i * 32 + lane;
            const float4 k0 = *(const float4*)&ks[(u * NKEYS + n) * HALFD];
            const float4 k1 = *(const float4*)&ks[(u * NKEYS + n) * HALFD + 4];
            s[i] = qv[0] * k0.x + qv[1] * k0.y + qv[2] * k0.z + qv[3] * k0.w
                 + qv[4] * k1.x + qv[5] * k1.y + qv[6] * k1.z + qv[7] * k1.w;
        }
#pragma unroll
        for (int r = 0; r < KNN; r++) {
            float bv = NEGINF; int bn = 0x7fffffff;
#pragma unroll
            for (int i = 0; i < 8; i++)
                if (s[i] > bv) { bv = s[i]; bn = i * 32 + lane; }
#pragma unroll
            for (int off = 16; off; off >>= 1) {
                const float ov = __shfl_xor_sync(0xffffffffu, bv, off);
                const int   on = __shfl_xor_sync(0xffffffffu, bn, off);
                if (ov > bv || (ov == bv && on < bn)) { bv = ov; bn = on; }
            }
            if (lane == 0) { sc_s[w][h][side][r] = bv; id_s[w][h][side][r] = bn; }
            if ((bn & 31) == lane) s[bn >> 5] = NEGINF;   // kill winner
        }
    }
    __syncwarp();

    // ---- Combine per head: 64 combos, top-8 ----
#pragma unroll
    for (int h = 0; h < 2; h++) {
        float v0 = sc_s[w][h][0][lane >> 3]       + sc_s[w][h][1][lane & 7];
        float v1 = sc_s[w][h][0][(lane >> 3) + 4] + sc_s[w][h][1][lane & 7];
#pragma unroll
        for (int r = 0; r < KNN; r++) {
            float bv = v0; int bc = lane;
            if (v1 > bv) { bv = v1; bc = lane + 32; }
#pragma unroll
            for (int off = 16; off; off >>= 1) {
                const float ov = __shfl_xor_sync(0xffffffffu, bv, off);
                const int   oc = __shfl_xor_sync(0xffffffffu, bc, off);
                if (ov > bv || (ov == bv && oc < bc)) { bv = ov; bc = oc; }
            }
            if (lane == 0) {
                fsc_s[w][h][r] = bv;
                const int a = bc >> 3, b = bc & 7;
                fid_s[w][h][r] = id_s[w][h][0][a] * NKEYS + id_s[w][h][1][b];
            }
            if (bc == lane)      v0 = NEGINF;
            if (bc == lane + 32) v1 = NEGINF;
        }
    }
    __syncwarp();

    // ---- softmax over 8 per head ----
    if (lane < 16) {
        const int h = lane >> 3, kk = lane & 7;
        float m = NEGINF;
#pragma unroll
        for (int i = 0; i < KNN; i++) m = fmaxf(m, fsc_s[w][h][i]);
        float den = 0.f;
#pragma unroll
        for (int i = 0; i < KNN; i++) den += expf(fsc_s[w][h][i] - m);
        const float wt = expf(fsc_s[w][h][kk] - m) / den;
        g_wt[t * 16 + lane] = wt;
        g_id[t * 16 + lane] = fid_s[w][h][kk];
    }
}

// ---------------------------------------------------------------------------
// Kernel 4: out[t] = sum_{k<16} w_k * values[idx_k]
// Persistent blocks (grid = 148*3 to match reg-limited occupancy), double-
// buffered metadata, 16-deep independent LDG.128 per thread.
// ---------------------------------------------------------------------------
#define K4_GRID 444

__global__ __launch_bounds__(256)
void k4_gather(const float* __restrict__ values, float* __restrict__ out)
{
    __shared__ float ws[2][16];
    __shared__ int   is[2][16];

    const int tid = threadIdx.x;
    const int col = tid << 2;

    int t = blockIdx.x;
    if (tid < 16) {
        ws[0][tid] = g_wt[t * 16 + tid];
        is[0][tid] = g_id[t * 16 + tid];
    }
    __syncthreads();

    int buf = 0;
    for (; t < T_TOK; t += K4_GRID, buf ^= 1) {
        const int tn = t + K4_GRID;
        if (tid < 16 && tn < T_TOK) {
            ws[buf ^ 1][tid] = g_wt[tn * 16 + tid];
            is[buf ^ 1][tid] = g_id[tn * 16 + tid];
        }
        float4 acc = make_float4(0.f, 0.f, 0.f, 0.f);
#pragma unroll
        for (int k = 0; k < 16; k++) {
            const float4 v =
                __ldg((const float4*)(values + (size_t)is[buf][k] * D_IN + col));
            const float wk = ws[buf][k];
            acc.x = fmaf(wk, v.x, acc.x);
            acc.y = fmaf(wk, v.y, acc.y);
            acc.z = fmaf(wk, v.z, acc.z);
            acc.w = fmaf(wk, v.w, acc.w);
        }
        *(float4*)(out + (size_t)t * D_IN + col) = acc;
        __syncthreads();
    }
}

// ---------------------------------------------------------------------------
extern "C" void kernel_launch(void* const* d_in, const int* in_sizes, int n_in,
                              void* d_out, int out_size)
{
    const float* x      = (const float*)d_in[0];
    const float* W1     = (const float*)d_in[1];
    const float* b1     = (const float*)d_in[2];
    const float* W2     = (const float*)d_in[3];
    const float* b2     = (const float*)d_in[4];
    const float* keys   = (const float*)d_in[5];
    const float* values = (const float*)d_in[6];
    float* out = (float*)d_out;

    k1_gemm_relu<<<T_TOK / BM, 128>>>(x, W1, b1);
    k3_topk<<<T_TOK / 8, 256>>>(keys, W2, b2);
    k4_gather<<<K4_GRID, 256>>>(values, out);
}